// round 3
// baseline (speedup 1.0000x reference)
#include <cuda_runtime.h>

// ---------------------------------------------------------------------------
// 2-layer GCN collapsed to scalar graph ops (feature dims 1 -> H -> 1;
// aggregation is linear so each layer is a scalar scatter-add).
//   deg[v]   = #in-edges + 1 (self loop)
//   dis[v]   = rsqrt(deg[v])
//   s1[v]    = dis[v] * ( sum_{u->v} dis[u]*x[u]  +  dis[v]*x[v] )
//   t[v]     = sum_k relu(s1[v]*W1[k] + b1[k]) * W2[k]
//   out[v]   = dis[v] * ( sum_{u->v} dis[u]*t[u]  +  dis[v]*t[v] ) + b2
// edge_index arrives as int32. L2-bound: maximize per-thread MLP.
// ---------------------------------------------------------------------------

#define MAXN 100352   // >= N_NODES (100000)

__device__ float g_deg[MAXN];
__device__ float g_dis[MAXN];
__device__ float g_val[MAXN];   // pre-scaled message value (dis[u]*feat[u])
__device__ float g_acc[MAXN];   // scatter accumulator

// ---- degree pass: 8 edges/thread, batched 128-bit index loads -------------
__global__ void k_deg8(const int* __restrict__ dst, int E) {
    int base = (blockIdx.x * blockDim.x + threadIdx.x) * 8;
    if (base + 8 <= E) {
        int4 d0 = *reinterpret_cast<const int4*>(dst + base);
        int4 d1 = *reinterpret_cast<const int4*>(dst + base + 4);
        atomicAdd(&g_deg[d0.x], 1.0f);
        atomicAdd(&g_deg[d0.y], 1.0f);
        atomicAdd(&g_deg[d0.z], 1.0f);
        atomicAdd(&g_deg[d0.w], 1.0f);
        atomicAdd(&g_deg[d1.x], 1.0f);
        atomicAdd(&g_deg[d1.y], 1.0f);
        atomicAdd(&g_deg[d1.z], 1.0f);
        atomicAdd(&g_deg[d1.w], 1.0f);
    } else {
        for (int i = base; i < E; ++i) atomicAdd(&g_deg[dst[i]], 1.0f);
    }
}

// ---- scatter pass: acc[dst] += val[src], 8 edges/thread --------------------
__global__ void k_edge8(const int* __restrict__ src,
                        const int* __restrict__ dst, int E) {
    int base = (blockIdx.x * blockDim.x + threadIdx.x) * 8;
    if (base + 8 <= E) {
        int4 s0 = *reinterpret_cast<const int4*>(src + base);
        int4 s1 = *reinterpret_cast<const int4*>(src + base + 4);
        int4 d0 = *reinterpret_cast<const int4*>(dst + base);
        int4 d1 = *reinterpret_cast<const int4*>(dst + base + 4);
        // batch all gathers first -> 8 outstanding LDGs per thread
        float v0 = __ldg(&g_val[s0.x]);
        float v1 = __ldg(&g_val[s0.y]);
        float v2 = __ldg(&g_val[s0.z]);
        float v3 = __ldg(&g_val[s0.w]);
        float v4 = __ldg(&g_val[s1.x]);
        float v5 = __ldg(&g_val[s1.y]);
        float v6 = __ldg(&g_val[s1.z]);
        float v7 = __ldg(&g_val[s1.w]);
        atomicAdd(&g_acc[d0.x], v0);
        atomicAdd(&g_acc[d0.y], v1);
        atomicAdd(&g_acc[d0.z], v2);
        atomicAdd(&g_acc[d0.w], v3);
        atomicAdd(&g_acc[d1.x], v4);
        atomicAdd(&g_acc[d1.y], v5);
        atomicAdd(&g_acc[d1.z], v6);
        atomicAdd(&g_acc[d1.w], v7);
    } else {
        for (int i = base; i < E; ++i)
            atomicAdd(&g_acc[dst[i]], __ldg(&g_val[src[i]]));
    }
}

// ---- node kernels ----------------------------------------------------------
__global__ void k_nodeA(const float* __restrict__ x, int n) {
    int v = blockIdx.x * blockDim.x + threadIdx.x;
    if (v < n) {
        float d = rsqrtf(g_deg[v] + 1.0f);   // +1 self-loop; always >= 1
        g_dis[v] = d;
        g_val[v] = d * x[v];
        g_acc[v] = 0.0f;
    }
}

__global__ void k_nodeB(const float* __restrict__ W1,
                        const float* __restrict__ b1,
                        const float* __restrict__ W2,
                        int H, int n) {
    __shared__ float sw1[256], sb1[256], sw2[256];
    for (int k = threadIdx.x; k < H && k < 256; k += blockDim.x) {
        sw1[k] = W1[k];
        sb1[k] = b1[k];
        sw2[k] = W2[k];
    }
    __syncthreads();
    int v = blockIdx.x * blockDim.x + threadIdx.x;
    if (v < n) {
        float d = g_dis[v];
        float s = d * (g_acc[v] + g_val[v]);
        float t = 0.0f;
        #pragma unroll 8
        for (int k = 0; k < H; ++k)
            t += fmaxf(fmaf(s, sw1[k], sb1[k]), 0.0f) * sw2[k];
        g_val[v] = d * t;
        g_acc[v] = 0.0f;
    }
}

__global__ void k_nodeC(float* __restrict__ out, const float* __restrict__ b2,
                        int n) {
    int v = blockIdx.x * blockDim.x + threadIdx.x;
    if (v < n) out[v] = g_dis[v] * (g_acc[v] + g_val[v]) + b2[0];
}

extern "C" void kernel_launch(void* const* d_in, const int* in_sizes, int n_in,
                              void* d_out, int out_size) {
    const float* x  = (const float*)d_in[0];
    const int*   ei = (const int*)d_in[1];     // int32 edge indices
    const float* W1 = (const float*)d_in[2];
    const float* b1 = (const float*)d_in[3];
    const float* W2 = (const float*)d_in[4];
    const float* b2 = (const float*)d_in[5];
    float*       out = (float*)d_out;

    int n = in_sizes[0];          // N nodes
    int E = in_sizes[1] / 2;      // edge_index is [2,E]
    int H = in_sizes[2];          // hidden width, <= 256

    const int* src = ei;
    const int* dst = ei + E;

    const int TB = 256;
    int nb = (n + TB - 1) / TB;
    int et = (E + 7) / 8;                 // threads for 8-edge kernels
    int eb = (et + TB - 1) / TB;

    // zero g_deg via memset (capturable, no extra kernel)
    void* degp = nullptr;
    cudaGetSymbolAddress(&degp, g_deg);
    cudaMemsetAsync(degp, 0, (size_t)n * sizeof(float));

    if (((E & 3) == 0)) {                 // 16B alignment of dst half
        k_deg8<<<eb, TB>>>(dst, E);
        k_nodeA<<<nb, TB>>>(x, n);
        k_edge8<<<eb, TB>>>(src, dst, E);
        k_nodeB<<<nb, TB>>>(W1, b1, W2, H, n);
        k_edge8<<<eb, TB>>>(src, dst, E);
        k_nodeC<<<nb, TB>>>(out, b2, n);
    } else {
        // unaligned fallback: scalar within the same kernels (base>=E path
        // never vectorizes, but grid covers all edges via the tail loop)
        k_deg8<<<eb, TB>>>(dst, E);
        k_nodeA<<<nb, TB>>>(x, n);
        k_edge8<<<eb, TB>>>(src, dst, E);
        k_nodeB<<<nb, TB>>>(W1, b1, W2, H, n);
        k_edge8<<<eb, TB>>>(src, dst, E);
        k_nodeC<<<nb, TB>>>(out, b2, n);
    }
}

// round 4
// speedup vs baseline: 1.0014x; 1.0014x over previous
#include <cuda_runtime.h>

// ---------------------------------------------------------------------------
// 2-layer GCN collapsed to scalar graph ops (feature dims 1 -> H -> 1;
// aggregation is linear so each layer is a scalar scatter-add).
//   deg[v]   = #in-edges + 1 (self loop)
//   dis[v]   = rsqrt(deg[v])
//   s1[v]    = dis[v] * ( sum_{u->v} dis[u]*x[u]  +  dis[v]*x[v] )
//   t[v]     = sum_k relu(s1[v]*W1[k] + b1[k]) * W2[k]
//   out[v]   = dis[v] * ( sum_{u->v} dis[u]*t[u]  +  dis[v]*t[v] ) + b2
// edge_index arrives as int32. Edge passes sit at the REDG + L1tex-wavefront
// structural floor (~2.3 cyc/edge/SM); 4 edges/thread @ 256 threads is the
// measured-best config. nodeB parallelized 8 threads/node.
// ---------------------------------------------------------------------------

#define MAXN 100352   // >= N_NODES (100000)

__device__ float g_deg[MAXN];
__device__ float g_dis[MAXN];
__device__ float g_val[MAXN];   // pre-scaled message value (dis[u]*feat[u])
__device__ float g_acc[MAXN];   // scatter accumulator

// ---- degree pass: 4 edges/thread via 128-bit index loads -------------------
__global__ void k_deg4(const int* __restrict__ dst, int E) {
    int i = (blockIdx.x * blockDim.x + threadIdx.x) * 4;
    if (i + 3 < E) {
        int4 d = *reinterpret_cast<const int4*>(dst + i);
        atomicAdd(&g_deg[d.x], 1.0f);
        atomicAdd(&g_deg[d.y], 1.0f);
        atomicAdd(&g_deg[d.z], 1.0f);
        atomicAdd(&g_deg[d.w], 1.0f);
    } else {
        for (; i < E; ++i) atomicAdd(&g_deg[dst[i]], 1.0f);
    }
}

// ---- scatter pass: acc[dst] += val[src], 4 edges/thread --------------------
__global__ void k_edge4(const int* __restrict__ src,
                        const int* __restrict__ dst, int E) {
    int i = (blockIdx.x * blockDim.x + threadIdx.x) * 4;
    if (i + 3 < E) {
        int4 s = *reinterpret_cast<const int4*>(src + i);
        int4 d = *reinterpret_cast<const int4*>(dst + i);
        float v0 = __ldg(&g_val[s.x]);
        float v1 = __ldg(&g_val[s.y]);
        float v2 = __ldg(&g_val[s.z]);
        float v3 = __ldg(&g_val[s.w]);
        atomicAdd(&g_acc[d.x], v0);
        atomicAdd(&g_acc[d.y], v1);
        atomicAdd(&g_acc[d.z], v2);
        atomicAdd(&g_acc[d.w], v3);
    } else {
        for (; i < E; ++i)
            atomicAdd(&g_acc[dst[i]], __ldg(&g_val[src[i]]));
    }
}

// ---- node kernels -----------------------------------------------------------
__global__ void k_nodeA(const float* __restrict__ x, int n) {
    int v = blockIdx.x * blockDim.x + threadIdx.x;
    if (v < n) {
        float d = rsqrtf(g_deg[v] + 1.0f);   // +1 self-loop; always >= 1
        g_dis[v] = d;
        g_val[v] = d * x[v];
        g_acc[v] = 0.0f;
    }
}

// 8 threads per node: thread 'part' covers k = part, part+8, ... (stride-8
// -> 8 distinct banks per warp-LDS, 4-node broadcast per address). Partial
// sums reduced with width-8 shfl.
__global__ void k_nodeB(const float* __restrict__ W1,
                        const float* __restrict__ b1,
                        const float* __restrict__ W2,
                        int H, int n) {
    __shared__ float sw1[256], sb1[256], sw2[256];
    for (int k = threadIdx.x; k < H && k < 256; k += blockDim.x) {
        sw1[k] = W1[k];
        sb1[k] = b1[k];
        sw2[k] = W2[k];
    }
    __syncthreads();
    int gid  = blockIdx.x * blockDim.x + threadIdx.x;
    int v    = gid >> 3;
    int part = gid & 7;
    float d = 0.0f, s = 0.0f;
    if (v < n) {
        d = g_dis[v];
        s = d * (g_acc[v] + g_val[v]);
    }
    float t = 0.0f;
    #pragma unroll 8
    for (int k = part; k < H; k += 8)
        t += fmaxf(fmaf(s, sw1[k], sb1[k]), 0.0f) * sw2[k];
    // reduce across the 8 lanes that share a node (lanes are contiguous)
    t += __shfl_down_sync(0xFFFFFFFFu, t, 4, 8);
    t += __shfl_down_sync(0xFFFFFFFFu, t, 2, 8);
    t += __shfl_down_sync(0xFFFFFFFFu, t, 1, 8);
    if (v < n && part == 0) {
        g_val[v] = d * t;
        g_acc[v] = 0.0f;
    }
}

__global__ void k_nodeC(float* __restrict__ out, const float* __restrict__ b2,
                        int n) {
    int v = blockIdx.x * blockDim.x + threadIdx.x;
    if (v < n) out[v] = g_dis[v] * (g_acc[v] + g_val[v]) + b2[0];
}

extern "C" void kernel_launch(void* const* d_in, const int* in_sizes, int n_in,
                              void* d_out, int out_size) {
    const float* x  = (const float*)d_in[0];
    const int*   ei = (const int*)d_in[1];     // int32 edge indices
    const float* W1 = (const float*)d_in[2];
    const float* b1 = (const float*)d_in[3];
    const float* W2 = (const float*)d_in[4];
    const float* b2 = (const float*)d_in[5];
    float*       out = (float*)d_out;

    int n = in_sizes[0];          // N nodes
    int E = in_sizes[1] / 2;      // edge_index is [2,E]
    int H = in_sizes[2];          // hidden width, <= 256

    const int* src = ei;
    const int* dst = ei + E;

    const int TB = 256;
    int nb  = (n + TB - 1) / TB;
    int nb8 = ((n * 8) + TB - 1) / TB;       // 8 threads per node for nodeB
    int et  = (E + 3) / 4;
    int eb  = (et + TB - 1) / TB;

    // zero g_deg via async memset (capturable)
    void* degp = nullptr;
    cudaGetSymbolAddress(&degp, g_deg);
    cudaMemsetAsync(degp, 0, (size_t)n * sizeof(float));

    k_deg4<<<eb, TB>>>(dst, E);
    k_nodeA<<<nb, TB>>>(x, n);
    k_edge4<<<eb, TB>>>(src, dst, E);
    k_nodeB<<<nb8, TB>>>(W1, b1, W2, H, n);
    k_edge4<<<eb, TB>>>(src, dst, E);
    k_nodeC<<<nb, TB>>>(out, b2, n);
}

// round 5
// speedup vs baseline: 1.0426x; 1.0412x over previous
#include <cuda_runtime.h>
#include <math_constants.h>

// ---------------------------------------------------------------------------
// 2-layer GCN collapsed to scalar graph ops (feature dims 1 -> H -> 1).
//   deg[v] = #in-edges + 1 ; dis[v] = rsqrt(deg[v])
//   s1[v]  = dis[v] * ( sum_{u->v} dis[u]*x[u] + dis[v]*x[v] )
//   t[v]   = sum_k relu(s1[v]*W1[k] + b1[k]) * W2[k]      <-- piecewise-linear
//   out[v] = dis[v] * ( sum_{u->v} dis[u]*t[u] + dis[v]*t[v] ) + b2
// t(s) is piecewise linear in s: precompute sorted breakpoints + per-segment
// (A,B) so nodeB is a binary search + FMA instead of a 256-iteration loop.
// ---------------------------------------------------------------------------

#define MAXN 100352   // >= N_NODES (100000)
#define MAXH 256

__device__ float g_deg[MAXN];
__device__ float g_dis[MAXN];
__device__ float g_val[MAXN];   // pre-scaled message value (dis[u]*feat[u])
__device__ float g_acc[MAXN];   // scatter accumulator

__device__ float g_pw_c[MAXH];      // sorted breakpoints
__device__ float g_pw_A[MAXH + 1];  // segment slopes
__device__ float g_pw_B[MAXH + 1];  // segment intercepts

// ---- piecewise-linear table build: one block of MAXH threads ---------------
__global__ void k_prep(const float* __restrict__ W1,
                       const float* __restrict__ b1,
                       const float* __restrict__ W2, int H) {
    __shared__ float sc[MAXH];            // breakpoint keys
    __shared__ float sdA[MAXH], sdB[MAXH]; // deltas crossing each breakpoint
    __shared__ float sA[MAXH], sB[MAXH];   // scan buffers
    __shared__ float s_base[2];            // A0, B0

    int i = threadIdx.x;

    // per-k terms
    float w1 = (i < H) ? W1[i] : 0.0f;
    float bb = (i < H) ? b1[i] : 0.0f;
    float w2 = (i < H) ? W2[i] : 0.0f;
    float aa = w1 * w2;     // slope contribution
    float cc = bb * w2;     // intercept contribution

    float key, dA, dB;
    float base_A = 0.0f, base_B = 0.0f;
    if (i < H && w1 > 0.0f) {
        key = -bb / w1; dA = aa;  dB = cc;       // activates when s > key
    } else if (i < H && w1 < 0.0f) {
        key = -bb / w1; dA = -aa; dB = -cc;      // deactivates when s > key
        base_A = aa; base_B = cc;                // active at s = -inf
    } else {
        key = CUDART_INF_F; dA = 0.0f; dB = 0.0f;
        if (i < H && bb > 0.0f) base_B = cc;     // constant-active term
    }
    sc[i] = key; sdA[i] = dA; sdB[i] = dB;
    sA[i] = base_A; sB[i] = base_B;
    __syncthreads();

    // block reduction for base (A0, B0)
    for (int off = MAXH / 2; off > 0; off >>= 1) {
        if (i < off) { sA[i] += sA[i + off]; sB[i] += sB[i + off]; }
        __syncthreads();
    }
    if (i == 0) { s_base[0] = sA[0]; s_base[1] = sB[0]; }
    __syncthreads();

    // bitonic sort (key ascending, payload dA,dB)
    for (int k = 2; k <= MAXH; k <<= 1) {
        for (int j = k >> 1; j > 0; j >>= 1) {
            int ixj = i ^ j;
            if (ixj > i) {
                bool up = ((i & k) == 0);
                if ((sc[i] > sc[ixj]) == up) {
                    float tk = sc[i];  sc[i]  = sc[ixj];  sc[ixj]  = tk;
                    float ta = sdA[i]; sdA[i] = sdA[ixj]; sdA[ixj] = ta;
                    float tb = sdB[i]; sdB[i] = sdB[ixj]; sdB[ixj] = tb;
                }
            }
            __syncthreads();
        }
    }

    // inclusive Hillis–Steele scan of (dA, dB)
    float pa = sdA[i], pb = sdB[i];
    sA[i] = pa; sB[i] = pb;
    __syncthreads();
    for (int off = 1; off < MAXH; off <<= 1) {
        float na = sA[i], nb = sB[i];
        if (i >= off) { na += sA[i - off]; nb += sB[i - off]; }
        __syncthreads();
        sA[i] = na; sB[i] = nb;
        __syncthreads();
    }

    // emit tables: A[j], B[j] valid for segment with j breakpoints <= s
    g_pw_c[i] = sc[i];
    g_pw_A[i + 1] = s_base[0] + sA[i];
    g_pw_B[i + 1] = s_base[1] + sB[i];
    if (i == 0) { g_pw_A[0] = s_base[0]; g_pw_B[0] = s_base[1]; }
}

// ---- degree pass: 4 edges/thread via 128-bit index loads -------------------
__global__ void k_deg4(const int* __restrict__ dst, int E) {
    int i = (blockIdx.x * blockDim.x + threadIdx.x) * 4;
    if (i + 3 < E) {
        int4 d = *reinterpret_cast<const int4*>(dst + i);
        atomicAdd(&g_deg[d.x], 1.0f);
        atomicAdd(&g_deg[d.y], 1.0f);
        atomicAdd(&g_deg[d.z], 1.0f);
        atomicAdd(&g_deg[d.w], 1.0f);
    } else {
        for (; i < E; ++i) atomicAdd(&g_deg[dst[i]], 1.0f);
    }
}

// ---- scatter pass: acc[dst] += val[src], 4 edges/thread --------------------
__global__ void k_edge4(const int* __restrict__ src,
                        const int* __restrict__ dst, int E) {
    int i = (blockIdx.x * blockDim.x + threadIdx.x) * 4;
    if (i + 3 < E) {
        int4 s = *reinterpret_cast<const int4*>(src + i);
        int4 d = *reinterpret_cast<const int4*>(dst + i);
        float v0 = __ldg(&g_val[s.x]);
        float v1 = __ldg(&g_val[s.y]);
        float v2 = __ldg(&g_val[s.z]);
        float v3 = __ldg(&g_val[s.w]);
        atomicAdd(&g_acc[d.x], v0);
        atomicAdd(&g_acc[d.y], v1);
        atomicAdd(&g_acc[d.z], v2);
        atomicAdd(&g_acc[d.w], v3);
    } else {
        for (; i < E; ++i)
            atomicAdd(&g_acc[dst[i]], __ldg(&g_val[src[i]]));
    }
}

// ---- node kernels -----------------------------------------------------------
__global__ void k_nodeA(const float* __restrict__ x, int n) {
    int v = blockIdx.x * blockDim.x + threadIdx.x;
    if (v < n) {
        float d = rsqrtf(g_deg[v] + 1.0f);   // +1 self-loop; always >= 1
        g_dis[v] = d;
        g_val[v] = d * x[v];
        g_acc[v] = 0.0f;
    }
}

// nodeB: binary-search the piecewise-linear table, t = A_j*s + B_j
__global__ void k_nodeB(int H, int n) {
    __shared__ float sc[MAXH], sA[MAXH + 1], sB[MAXH + 1];
    for (int k = threadIdx.x; k < MAXH; k += blockDim.x) {
        sc[k] = g_pw_c[k];
        sA[k] = g_pw_A[k];
        sB[k] = g_pw_B[k];
    }
    if (threadIdx.x == 0) { sA[MAXH] = g_pw_A[MAXH]; sB[MAXH] = g_pw_B[MAXH]; }
    __syncthreads();
    int v = blockIdx.x * blockDim.x + threadIdx.x;
    if (v < n) {
        float d = g_dis[v];
        float s = d * (g_acc[v] + g_val[v]);
        // j = number of breakpoints <= s  (c sorted ascending, pad = +inf)
        int lo = 0, hi = MAXH;
        #pragma unroll
        for (int step = 0; step < 8; ++step) {
            int mid = (lo + hi) >> 1;
            if (sc[mid] <= s) lo = mid + 1; else hi = mid;
        }
        float t = fmaf(sA[lo], s, sB[lo]);
        g_val[v] = d * t;
        g_acc[v] = 0.0f;
    }
}

__global__ void k_nodeC(float* __restrict__ out, const float* __restrict__ b2,
                        int n) {
    int v = blockIdx.x * blockDim.x + threadIdx.x;
    if (v < n) out[v] = g_dis[v] * (g_acc[v] + g_val[v]) + b2[0];
}

extern "C" void kernel_launch(void* const* d_in, const int* in_sizes, int n_in,
                              void* d_out, int out_size) {
    const float* x  = (const float*)d_in[0];
    const int*   ei = (const int*)d_in[1];     // int32 edge indices
    const float* W1 = (const float*)d_in[2];
    const float* b1 = (const float*)d_in[3];
    const float* W2 = (const float*)d_in[4];
    const float* b2 = (const float*)d_in[5];
    float*       out = (float*)d_out;

    int n = in_sizes[0];          // N nodes
    int E = in_sizes[1] / 2;      // edge_index is [2,E]
    int H = in_sizes[2];          // hidden width, <= 256

    const int* src = ei;
    const int* dst = ei + E;

    const int TB = 256;
    int nb = (n + TB - 1) / TB;
    int et = (E + 3) / 4;
    int eb = (et + TB - 1) / TB;

    // zero g_deg via async memset (capturable)
    void* degp = nullptr;
    cudaGetSymbolAddress(&degp, g_deg);
    cudaMemsetAsync(degp, 0, (size_t)n * sizeof(float));

    k_prep<<<1, MAXH>>>(W1, b1, W2, H);      // overlaps nothing but is tiny
    k_deg4<<<eb, TB>>>(dst, E);
    k_nodeA<<<nb, TB>>>(x, n);
    k_edge4<<<eb, TB>>>(src, dst, E);
    k_nodeB<<<nb, TB>>>(H, n);
    k_edge4<<<eb, TB>>>(src, dst, E);
    k_nodeC<<<nb, TB>>>(out, b2, n);
}

// round 6
// speedup vs baseline: 1.1212x; 1.0754x over previous
#include <cuda_runtime.h>
#include <cuda_fp16.h>
#include <math_constants.h>

// ---------------------------------------------------------------------------
// 2-layer GCN collapsed to scalar graph ops (feature dims 1 -> H -> 1).
//   deg[v] = #in-edges + 1 ; dis[v] = rsqrt(deg[v])
//   s1[v]  = dis[v] * ( sum_{u->v} dis[u]*x[u] + dis[v]*x[v] )
//   t[v]   = PW(s1[v])  (piecewise-linear collapse of relu-MLP)
//   out[v] = dis[v] * ( sum_{u->v} dis[u]*t[u] + dis[v]*t[v] ) + b2
// Edge passes are LTS-atomic-bound (~23us/pass floor for 3.2M RMWs). The
// gather side is moved into L1 by keeping a 200KB fp16 copy of the message
// values (fits L1), with fp32 copies kept for self-terms / accumulators.
// ---------------------------------------------------------------------------

#define MAXN 100352   // >= N_NODES (100000)
#define MAXH 256

__device__ float  g_deg[MAXN];
__device__ float  g_dis[MAXN];
__device__ float  g_val[MAXN];    // fp32 message value (self-term use)
__device__ __half g_valh[MAXN];   // fp16 copy for L1-resident gathers
__device__ float  g_acc[MAXN];    // scatter accumulator (fp32)

__device__ float g_pw_c[MAXH];      // sorted breakpoints
__device__ float g_pw_A[MAXH + 1];  // segment slopes
__device__ float g_pw_B[MAXH + 1];  // segment intercepts

// ---- piecewise-linear table build: one block of MAXH threads ---------------
__global__ void k_prep(const float* __restrict__ W1,
                       const float* __restrict__ b1,
                       const float* __restrict__ W2, int H) {
    __shared__ float sc[MAXH];
    __shared__ float sdA[MAXH], sdB[MAXH];
    __shared__ float sA[MAXH], sB[MAXH];
    __shared__ float s_base[2];

    int i = threadIdx.x;

    float w1 = (i < H) ? W1[i] : 0.0f;
    float bb = (i < H) ? b1[i] : 0.0f;
    float w2 = (i < H) ? W2[i] : 0.0f;
    float aa = w1 * w2;
    float cc = bb * w2;

    float key, dA, dB;
    float base_A = 0.0f, base_B = 0.0f;
    if (i < H && w1 > 0.0f) {
        key = -bb / w1; dA = aa;  dB = cc;
    } else if (i < H && w1 < 0.0f) {
        key = -bb / w1; dA = -aa; dB = -cc;
        base_A = aa; base_B = cc;
    } else {
        key = CUDART_INF_F; dA = 0.0f; dB = 0.0f;
        if (i < H && bb > 0.0f) base_B = cc;
    }
    sc[i] = key; sdA[i] = dA; sdB[i] = dB;
    sA[i] = base_A; sB[i] = base_B;
    __syncthreads();

    for (int off = MAXH / 2; off > 0; off >>= 1) {
        if (i < off) { sA[i] += sA[i + off]; sB[i] += sB[i + off]; }
        __syncthreads();
    }
    if (i == 0) { s_base[0] = sA[0]; s_base[1] = sB[0]; }
    __syncthreads();

    for (int k = 2; k <= MAXH; k <<= 1) {
        for (int j = k >> 1; j > 0; j >>= 1) {
            int ixj = i ^ j;
            if (ixj > i) {
                bool up = ((i & k) == 0);
                if ((sc[i] > sc[ixj]) == up) {
                    float tk = sc[i];  sc[i]  = sc[ixj];  sc[ixj]  = tk;
                    float ta = sdA[i]; sdA[i] = sdA[ixj]; sdA[ixj] = ta;
                    float tb = sdB[i]; sdB[i] = sdB[ixj]; sdB[ixj] = tb;
                }
            }
            __syncthreads();
        }
    }

    float pa = sdA[i], pb = sdB[i];
    sA[i] = pa; sB[i] = pb;
    __syncthreads();
    for (int off = 1; off < MAXH; off <<= 1) {
        float na = sA[i], nb = sB[i];
        if (i >= off) { na += sA[i - off]; nb += sB[i - off]; }
        __syncthreads();
        sA[i] = na; sB[i] = nb;
        __syncthreads();
    }

    g_pw_c[i] = sc[i];
    g_pw_A[i + 1] = s_base[0] + sA[i];
    g_pw_B[i + 1] = s_base[1] + sB[i];
    if (i == 0) { g_pw_A[0] = s_base[0]; g_pw_B[0] = s_base[1]; }
}

// ---- degree pass: 4 edges/thread via 128-bit index loads -------------------
__global__ void k_deg4(const int* __restrict__ dst, int E) {
    int i = (blockIdx.x * blockDim.x + threadIdx.x) * 4;
    if (i + 3 < E) {
        int4 d = *reinterpret_cast<const int4*>(dst + i);
        atomicAdd(&g_deg[d.x], 1.0f);
        atomicAdd(&g_deg[d.y], 1.0f);
        atomicAdd(&g_deg[d.z], 1.0f);
        atomicAdd(&g_deg[d.w], 1.0f);
    } else {
        for (; i < E; ++i) atomicAdd(&g_deg[dst[i]], 1.0f);
    }
}

// ---- scatter pass: acc[dst] += valh[src], fp16 gathers (L1-resident) -------
__global__ void k_edge4(const int* __restrict__ src,
                        const int* __restrict__ dst, int E) {
    int i = (blockIdx.x * blockDim.x + threadIdx.x) * 4;
    if (i + 3 < E) {
        int4 s = *reinterpret_cast<const int4*>(src + i);
        int4 d = *reinterpret_cast<const int4*>(dst + i);
        float v0 = __half2float(__ldg(&g_valh[s.x]));
        float v1 = __half2float(__ldg(&g_valh[s.y]));
        float v2 = __half2float(__ldg(&g_valh[s.z]));
        float v3 = __half2float(__ldg(&g_valh[s.w]));
        atomicAdd(&g_acc[d.x], v0);
        atomicAdd(&g_acc[d.y], v1);
        atomicAdd(&g_acc[d.z], v2);
        atomicAdd(&g_acc[d.w], v3);
    } else {
        for (; i < E; ++i)
            atomicAdd(&g_acc[dst[i]], __half2float(__ldg(&g_valh[src[i]])));
    }
}

// ---- node kernels -----------------------------------------------------------
__global__ void k_nodeA(const float* __restrict__ x, int n) {
    int v = blockIdx.x * blockDim.x + threadIdx.x;
    if (v < n) {
        float d = rsqrtf(g_deg[v] + 1.0f);   // +1 self-loop
        float val = d * x[v];
        g_dis[v] = d;
        g_val[v] = val;
        g_valh[v] = __float2half_rn(val);
        g_acc[v] = 0.0f;
    }
}

// nodeB: binary-search the piecewise-linear table, t = A_j*s + B_j
__global__ void k_nodeB(int H, int n) {
    __shared__ float sc[MAXH], sA[MAXH + 1], sB[MAXH + 1];
    for (int k = threadIdx.x; k < MAXH; k += blockDim.x) {
        sc[k] = g_pw_c[k];
        sA[k] = g_pw_A[k];
        sB[k] = g_pw_B[k];
    }
    if (threadIdx.x == 0) { sA[MAXH] = g_pw_A[MAXH]; sB[MAXH] = g_pw_B[MAXH]; }
    __syncthreads();
    int v = blockIdx.x * blockDim.x + threadIdx.x;
    if (v < n) {
        float d = g_dis[v];
        float s = d * (g_acc[v] + g_val[v]);   // fp32 self-term
        int lo = 0, hi = MAXH;
        #pragma unroll
        for (int step = 0; step < 8; ++step) {
            int mid = (lo + hi) >> 1;
            if (sc[mid] <= s) lo = mid + 1; else hi = mid;
        }
        float t = fmaf(sA[lo], s, sB[lo]);
        float val = d * t;
        g_val[v] = val;
        g_valh[v] = __float2half_rn(val);
        g_acc[v] = 0.0f;
    }
}

__global__ void k_nodeC(float* __restrict__ out, const float* __restrict__ b2,
                        int n) {
    int v = blockIdx.x * blockDim.x + threadIdx.x;
    if (v < n) out[v] = g_dis[v] * (g_acc[v] + g_val[v]) + b2[0];
}

extern "C" void kernel_launch(void* const* d_in, const int* in_sizes, int n_in,
                              void* d_out, int out_size) {
    const float* x  = (const float*)d_in[0];
    const int*   ei = (const int*)d_in[1];     // int32 edge indices
    const float* W1 = (const float*)d_in[2];
    const float* b1 = (const float*)d_in[3];
    const float* W2 = (const float*)d_in[4];
    const float* b2 = (const float*)d_in[5];
    float*       out = (float*)d_out;

    int n = in_sizes[0];
    int E = in_sizes[1] / 2;
    int H = in_sizes[2];

    const int* src = ei;
    const int* dst = ei + E;

    const int TB = 256;
    int nb = (n + TB - 1) / TB;
    int et = (E + 3) / 4;
    int eb = (et + TB - 1) / TB;

    void* degp = nullptr;
    cudaGetSymbolAddress(&degp, g_deg);
    cudaMemsetAsync(degp, 0, (size_t)n * sizeof(float));

    k_prep<<<1, MAXH>>>(W1, b1, W2, H);
    k_deg4<<<eb, TB>>>(dst, E);
    k_nodeA<<<nb, TB>>>(x, n);
    k_edge4<<<eb, TB>>>(src, dst, E);
    k_nodeB<<<nb, TB>>>(H, n);
    k_edge4<<<eb, TB>>>(src, dst, E);
    k_nodeC<<<nb, TB>>>(out, b2, n);
}

// round 7
// speedup vs baseline: 1.1491x; 1.0248x over previous
#include <cuda_runtime.h>
#include <cuda_fp16.h>
#include <math_constants.h>

// ---------------------------------------------------------------------------
// 2-layer GCN collapsed to scalar graph ops (feature dims 1 -> H -> 1).
//   deg[v] = #in-edges + 1 ; dis[v] = rsqrt(deg[v])
//   s1[v]  = dis[v] * ( sum_{u->v} dis[u]*x[u] + dis[v]*x[v] )
//   t[v]   = PW(s1[v])  (piecewise-linear collapse of relu-MLP)
//   out[v] = dis[v] * ( sum_{u->v} dis[u]*t[u] + dis[v]*t[v] ) + b2
// Edge passes are per-SM LSU/REDG bound (~2 cyc/edge). fp16 message copy
// (200KB) is kept L1-resident; index streams use .cs (evict-first) so they
// do not displace the gather working set.
// ---------------------------------------------------------------------------

#define MAXN 100352   // >= N_NODES (100000)
#define MAXH 256

__device__ float  g_deg[MAXN];
__device__ float  g_dis[MAXN];
__device__ float  g_val[MAXN];    // fp32 message value (self-term use)
__device__ __half g_valh[MAXN];   // fp16 copy for L1-resident gathers
__device__ float  g_acc[MAXN];    // scatter accumulator (fp32)

__device__ float g_pw_c[MAXH];      // sorted breakpoints
__device__ float g_pw_A[MAXH + 1];  // segment slopes
__device__ float g_pw_B[MAXH + 1];  // segment intercepts

// ---- piecewise-linear table build: one block of MAXH threads ---------------
__global__ void k_prep(const float* __restrict__ W1,
                       const float* __restrict__ b1,
                       const float* __restrict__ W2, int H) {
    __shared__ float sc[MAXH];
    __shared__ float sdA[MAXH], sdB[MAXH];
    __shared__ float sA[MAXH], sB[MAXH];
    __shared__ float s_base[2];

    int i = threadIdx.x;

    float w1 = (i < H) ? W1[i] : 0.0f;
    float bb = (i < H) ? b1[i] : 0.0f;
    float w2 = (i < H) ? W2[i] : 0.0f;
    float aa = w1 * w2;
    float cc = bb * w2;

    float key, dA, dB;
    float base_A = 0.0f, base_B = 0.0f;
    if (i < H && w1 > 0.0f) {
        key = -bb / w1; dA = aa;  dB = cc;
    } else if (i < H && w1 < 0.0f) {
        key = -bb / w1; dA = -aa; dB = -cc;
        base_A = aa; base_B = cc;
    } else {
        key = CUDART_INF_F; dA = 0.0f; dB = 0.0f;
        if (i < H && bb > 0.0f) base_B = cc;
    }
    sc[i] = key; sdA[i] = dA; sdB[i] = dB;
    sA[i] = base_A; sB[i] = base_B;
    __syncthreads();

    for (int off = MAXH / 2; off > 0; off >>= 1) {
        if (i < off) { sA[i] += sA[i + off]; sB[i] += sB[i + off]; }
        __syncthreads();
    }
    if (i == 0) { s_base[0] = sA[0]; s_base[1] = sB[0]; }
    __syncthreads();

    for (int k = 2; k <= MAXH; k <<= 1) {
        for (int j = k >> 1; j > 0; j >>= 1) {
            int ixj = i ^ j;
            if (ixj > i) {
                bool up = ((i & k) == 0);
                if ((sc[i] > sc[ixj]) == up) {
                    float tk = sc[i];  sc[i]  = sc[ixj];  sc[ixj]  = tk;
                    float ta = sdA[i]; sdA[i] = sdA[ixj]; sdA[ixj] = ta;
                    float tb = sdB[i]; sdB[i] = sdB[ixj]; sdB[ixj] = tb;
                }
            }
            __syncthreads();
        }
    }

    float pa = sdA[i], pb = sdB[i];
    sA[i] = pa; sB[i] = pb;
    __syncthreads();
    for (int off = 1; off < MAXH; off <<= 1) {
        float na = sA[i], nb = sB[i];
        if (i >= off) { na += sA[i - off]; nb += sB[i - off]; }
        __syncthreads();
        sA[i] = na; sB[i] = nb;
        __syncthreads();
    }

    g_pw_c[i] = sc[i];
    g_pw_A[i + 1] = s_base[0] + sA[i];
    g_pw_B[i + 1] = s_base[1] + sB[i];
    if (i == 0) { g_pw_A[0] = s_base[0]; g_pw_B[0] = s_base[1]; }
}

// ---- degree pass: 4 edges/thread, streaming (.cs) index loads --------------
__global__ void k_deg4(const int* __restrict__ dst, int E) {
    int i = (blockIdx.x * blockDim.x + threadIdx.x) * 4;
    if (i + 3 < E) {
        int4 d = __ldcs(reinterpret_cast<const int4*>(dst + i));
        atomicAdd(&g_deg[d.x], 1.0f);
        atomicAdd(&g_deg[d.y], 1.0f);
        atomicAdd(&g_deg[d.z], 1.0f);
        atomicAdd(&g_deg[d.w], 1.0f);
    } else {
        for (; i < E; ++i) atomicAdd(&g_deg[__ldcs(dst + i)], 1.0f);
    }
}

// ---- scatter: acc[dst] += valh[src]; .cs index streams protect L1 ----------
__global__ void k_edge4(const int* __restrict__ src,
                        const int* __restrict__ dst, int E) {
    int i = (blockIdx.x * blockDim.x + threadIdx.x) * 4;
    if (i + 3 < E) {
        int4 s = __ldcs(reinterpret_cast<const int4*>(src + i));
        int4 d = __ldcs(reinterpret_cast<const int4*>(dst + i));
        float v0 = __half2float(__ldg(&g_valh[s.x]));
        float v1 = __half2float(__ldg(&g_valh[s.y]));
        float v2 = __half2float(__ldg(&g_valh[s.z]));
        float v3 = __half2float(__ldg(&g_valh[s.w]));
        atomicAdd(&g_acc[d.x], v0);
        atomicAdd(&g_acc[d.y], v1);
        atomicAdd(&g_acc[d.z], v2);
        atomicAdd(&g_acc[d.w], v3);
    } else {
        for (; i < E; ++i)
            atomicAdd(&g_acc[__ldcs(dst + i)],
                      __half2float(__ldg(&g_valh[__ldcs(src + i)])));
    }
}

// ---- node kernels -----------------------------------------------------------
__global__ void k_nodeA(const float* __restrict__ x, int n) {
    int v = blockIdx.x * blockDim.x + threadIdx.x;
    if (v < n) {
        float d = rsqrtf(g_deg[v] + 1.0f);   // +1 self-loop
        float val = d * x[v];
        g_dis[v] = d;
        g_val[v] = val;
        g_valh[v] = __float2half_rn(val);
        g_acc[v] = 0.0f;
    }
}

// nodeB: binary-search the piecewise-linear table, t = A_j*s + B_j
__global__ void k_nodeB(int H, int n) {
    __shared__ float sc[MAXH], sA[MAXH + 1], sB[MAXH + 1];
    for (int k = threadIdx.x; k < MAXH; k += blockDim.x) {
        sc[k] = g_pw_c[k];
        sA[k] = g_pw_A[k];
        sB[k] = g_pw_B[k];
    }
    if (threadIdx.x == 0) { sA[MAXH] = g_pw_A[MAXH]; sB[MAXH] = g_pw_B[MAXH]; }
    __syncthreads();
    int v = blockIdx.x * blockDim.x + threadIdx.x;
    if (v < n) {
        float d = g_dis[v];
        float s = d * (g_acc[v] + g_val[v]);   // fp32 self-term
        int lo = 0, hi = MAXH;
        #pragma unroll
        for (int step = 0; step < 8; ++step) {
            int mid = (lo + hi) >> 1;
            if (sc[mid] <= s) lo = mid + 1; else hi = mid;
        }
        float t = fmaf(sA[lo], s, sB[lo]);
        float val = d * t;
        g_val[v] = val;
        g_valh[v] = __float2half_rn(val);
        g_acc[v] = 0.0f;
    }
}

__global__ void k_nodeC(float* __restrict__ out, const float* __restrict__ b2,
                        int n) {
    int v = blockIdx.x * blockDim.x + threadIdx.x;
    if (v < n) out[v] = g_dis[v] * (g_acc[v] + g_val[v]) + b2[0];
}

extern "C" void kernel_launch(void* const* d_in, const int* in_sizes, int n_in,
                              void* d_out, int out_size) {
    const float* x  = (const float*)d_in[0];
    const int*   ei = (const int*)d_in[1];     // int32 edge indices
    const float* W1 = (const float*)d_in[2];
    const float* b1 = (const float*)d_in[3];
    const float* W2 = (const float*)d_in[4];
    const float* b2 = (const float*)d_in[5];
    float*       out = (float*)d_out;

    int n = in_sizes[0];
    int E = in_sizes[1] / 2;
    int H = in_sizes[2];

    const int* src = ei;
    const int* dst = ei + E;

    const int TB = 256;
    int nb = (n + TB - 1) / TB;
    int et = (E + 3) / 4;
    int eb = (et + TB - 1) / TB;

    void* degp = nullptr;
    cudaGetSymbolAddress(&degp, g_deg);

    k_prep<<<1, MAXH>>>(W1, b1, W2, H);          // tiny, off the hot chain
    cudaMemsetAsync(degp, 0, (size_t)n * sizeof(float));
    k_deg4<<<eb, TB>>>(dst, E);
    k_nodeA<<<nb, TB>>>(x, n);
    k_edge4<<<eb, TB>>>(src, dst, E);
    k_nodeB<<<nb, TB>>>(H, n);
    k_edge4<<<eb, TB>>>(src, dst, E);
    k_nodeC<<<nb, TB>>>(out, b2, n);
}

// round 8
// speedup vs baseline: 1.1788x; 1.0259x over previous
#include <cuda_runtime.h>
#include <cuda_fp16.h>
#include <math_constants.h>

// ---------------------------------------------------------------------------
// 2-layer GCN collapsed to scalar graph ops (feature dims 1 -> H -> 1).
//   deg[v] = #in-edges + 1 ; dis[v] = rsqrt(deg[v])
//   s1[v]  = dis[v] * ( sum_{u->v} dis[u]*x[u] + dis[v]*x[v] )
//   t[v]   = PW(s1[v])  (piecewise-linear collapse of relu-MLP)
//   out[v] = dis[v] * ( sum_{u->v} dis[u]*t[u] + dis[v]*t[v] ) + b2
// Edge passes are L1tex-wavefront bound (~2.2 wf/edge scatter, ~1.25 deg);
// fp16 gather copy keeps the 200KB message set L1-resident, .cs protects it
// from the streaming index reads. g_deg is zero-on-load and re-zeroed by
// nodeA after consumption (invariant maintained across calls -> no memset).
// k_prep rides as the last block of the deg launch (consumed 2 launches on).
// ---------------------------------------------------------------------------

#define MAXN 100352   // >= N_NODES (100000)
#define MAXH 256

__device__ float  g_deg[MAXN];    // zero-initialized at load; invariant: ==0 at call entry
__device__ float  g_dis[MAXN];
__device__ float  g_val[MAXN];    // fp32 message value (self-term use)
__device__ __half g_valh[MAXN];   // fp16 copy for L1-resident gathers
__device__ float  g_acc[MAXN];    // scatter accumulator (fp32)

__device__ float g_pw_c[MAXH];      // sorted breakpoints
__device__ float g_pw_A[MAXH + 1];  // segment slopes
__device__ float g_pw_B[MAXH + 1];  // segment intercepts

// ---- piecewise-linear table build (device func, run by one block) ----------
__device__ void prep_block(const float* __restrict__ W1,
                           const float* __restrict__ b1,
                           const float* __restrict__ W2, int H) {
    __shared__ float sc[MAXH];
    __shared__ float sdA[MAXH], sdB[MAXH];
    __shared__ float sA[MAXH], sB[MAXH];
    __shared__ float s_base[2];

    int i = threadIdx.x;

    float w1 = (i < H) ? W1[i] : 0.0f;
    float bb = (i < H) ? b1[i] : 0.0f;
    float w2 = (i < H) ? W2[i] : 0.0f;
    float aa = w1 * w2;
    float cc = bb * w2;

    float key, dA, dB;
    float base_A = 0.0f, base_B = 0.0f;
    if (i < H && w1 > 0.0f) {
        key = -bb / w1; dA = aa;  dB = cc;
    } else if (i < H && w1 < 0.0f) {
        key = -bb / w1; dA = -aa; dB = -cc;
        base_A = aa; base_B = cc;
    } else {
        key = CUDART_INF_F; dA = 0.0f; dB = 0.0f;
        if (i < H && bb > 0.0f) base_B = cc;
    }
    sc[i] = key; sdA[i] = dA; sdB[i] = dB;
    sA[i] = base_A; sB[i] = base_B;
    __syncthreads();

    for (int off = MAXH / 2; off > 0; off >>= 1) {
        if (i < off) { sA[i] += sA[i + off]; sB[i] += sB[i + off]; }
        __syncthreads();
    }
    if (i == 0) { s_base[0] = sA[0]; s_base[1] = sB[0]; }
    __syncthreads();

    for (int k = 2; k <= MAXH; k <<= 1) {
        for (int j = k >> 1; j > 0; j >>= 1) {
            int ixj = i ^ j;
            if (ixj > i) {
                bool up = ((i & k) == 0);
                if ((sc[i] > sc[ixj]) == up) {
                    float tk = sc[i];  sc[i]  = sc[ixj];  sc[ixj]  = tk;
                    float ta = sdA[i]; sdA[i] = sdA[ixj]; sdA[ixj] = ta;
                    float tb = sdB[i]; sdB[i] = sdB[ixj]; sdB[ixj] = tb;
                }
            }
            __syncthreads();
        }
    }

    float pa = sdA[i], pb = sdB[i];
    sA[i] = pa; sB[i] = pb;
    __syncthreads();
    for (int off = 1; off < MAXH; off <<= 1) {
        float na = sA[i], nb = sB[i];
        if (i >= off) { na += sA[i - off]; nb += sB[i - off]; }
        __syncthreads();
        sA[i] = na; sB[i] = nb;
        __syncthreads();
    }

    g_pw_c[i] = sc[i];
    g_pw_A[i + 1] = s_base[0] + sA[i];
    g_pw_B[i + 1] = s_base[1] + sB[i];
    if (i == 0) { g_pw_A[0] = s_base[0]; g_pw_B[0] = s_base[1]; }
}

// ---- degree pass + prep rider: last block builds the PW table --------------
__global__ void k_deg4(const int* __restrict__ dst, int E,
                       const float* __restrict__ W1,
                       const float* __restrict__ b1,
                       const float* __restrict__ W2, int H) {
    if (blockIdx.x == gridDim.x - 1) {      // prep rider block
        prep_block(W1, b1, W2, H);
        return;
    }
    int i = (blockIdx.x * blockDim.x + threadIdx.x) * 4;
    if (i + 3 < E) {
        int4 d = __ldcs(reinterpret_cast<const int4*>(dst + i));
        atomicAdd(&g_deg[d.x], 1.0f);
        atomicAdd(&g_deg[d.y], 1.0f);
        atomicAdd(&g_deg[d.z], 1.0f);
        atomicAdd(&g_deg[d.w], 1.0f);
    } else {
        for (; i < E; ++i) atomicAdd(&g_deg[__ldcs(dst + i)], 1.0f);
    }
}

// ---- scatter: acc[dst] += valh[src]; .cs index streams protect L1 ----------
__global__ void k_edge4(const int* __restrict__ src,
                        const int* __restrict__ dst, int E) {
    int i = (blockIdx.x * blockDim.x + threadIdx.x) * 4;
    if (i + 3 < E) {
        int4 s = __ldcs(reinterpret_cast<const int4*>(src + i));
        int4 d = __ldcs(reinterpret_cast<const int4*>(dst + i));
        float v0 = __half2float(__ldg(&g_valh[s.x]));
        float v1 = __half2float(__ldg(&g_valh[s.y]));
        float v2 = __half2float(__ldg(&g_valh[s.z]));
        float v3 = __half2float(__ldg(&g_valh[s.w]));
        atomicAdd(&g_acc[d.x], v0);
        atomicAdd(&g_acc[d.y], v1);
        atomicAdd(&g_acc[d.z], v2);
        atomicAdd(&g_acc[d.w], v3);
    } else {
        for (; i < E; ++i)
            atomicAdd(&g_acc[__ldcs(dst + i)],
                      __half2float(__ldg(&g_valh[__ldcs(src + i)])));
    }
}

// ---- node kernels -----------------------------------------------------------
// nodeA consumes g_deg and restores the ==0 invariant for the next call.
__global__ void k_nodeA(const float* __restrict__ x, int n) {
    int v = blockIdx.x * blockDim.x + threadIdx.x;
    if (v < n) {
        float d = rsqrtf(g_deg[v] + 1.0f);   // +1 self-loop
        g_deg[v] = 0.0f;                      // re-zero (line already in cache)
        float val = d * x[v];
        g_dis[v] = d;
        g_val[v] = val;
        g_valh[v] = __float2half_rn(val);
        g_acc[v] = 0.0f;
    }
}

// nodeB: binary-search the piecewise-linear table, t = A_j*s + B_j
__global__ void k_nodeB(int H, int n) {
    __shared__ float sc[MAXH], sA[MAXH + 1], sB[MAXH + 1];
    for (int k = threadIdx.x; k < MAXH; k += blockDim.x) {
        sc[k] = g_pw_c[k];
        sA[k] = g_pw_A[k];
        sB[k] = g_pw_B[k];
    }
    if (threadIdx.x == 0) { sA[MAXH] = g_pw_A[MAXH]; sB[MAXH] = g_pw_B[MAXH]; }
    __syncthreads();
    int v = blockIdx.x * blockDim.x + threadIdx.x;
    if (v < n) {
        float d = g_dis[v];
        float s = d * (g_acc[v] + g_val[v]);   // fp32 self-term
        int lo = 0, hi = MAXH;
        #pragma unroll
        for (int step = 0; step < 8; ++step) {
            int mid = (lo + hi) >> 1;
            if (sc[mid] <= s) lo = mid + 1; else hi = mid;
        }
        float t = fmaf(sA[lo], s, sB[lo]);
        float val = d * t;
        g_val[v] = val;
        g_valh[v] = __float2half_rn(val);
        g_acc[v] = 0.0f;
    }
}

__global__ void k_nodeC(float* __restrict__ out, const float* __restrict__ b2,
                        int n) {
    int v = blockIdx.x * blockDim.x + threadIdx.x;
    if (v < n) out[v] = g_dis[v] * (g_acc[v] + g_val[v]) + b2[0];
}

extern "C" void kernel_launch(void* const* d_in, const int* in_sizes, int n_in,
                              void* d_out, int out_size) {
    const float* x  = (const float*)d_in[0];
    const int*   ei = (const int*)d_in[1];     // int32 edge indices
    const float* W1 = (const float*)d_in[2];
    const float* b1 = (const float*)d_in[3];
    const float* W2 = (const float*)d_in[4];
    const float* b2 = (const float*)d_in[5];
    float*       out = (float*)d_out;

    int n = in_sizes[0];
    int E = in_sizes[1] / 2;
    int H = in_sizes[2];

    const int* src = ei;
    const int* dst = ei + E;

    const int TB = 256;   // == MAXH, required by the prep rider block
    int nb = (n + TB - 1) / TB;
    int et = (E + 3) / 4;
    int eb = (et + TB - 1) / TB;

    k_deg4<<<eb + 1, TB>>>(dst, E, W1, b1, W2, H);   // +1 prep rider block
    k_nodeA<<<nb, TB>>>(x, n);
    k_edge4<<<eb, TB>>>(src, dst, E);
    k_nodeB<<<nb, TB>>>(H, n);
    k_edge4<<<eb, TB>>>(src, dst, E);
    k_nodeC<<<nb, TB>>>(out, b2, n);
}